// round 10
// baseline (speedup 1.0000x reference)
#include <cuda_runtime.h>

#define B_   8
#define H_   1024
#define W_   1024
#define NW_  32                      // 32-bit words per column (H/32)
#define NWG  34                      // NW_ + 2 guard word-rows (always zero)
#define NPIX (B_ * H_ * W_)
#define RAD  7                       // truncation radius; rel err ~2e-4 << 1e-3

#define NBLK (B_ * H_ / 2)           // 4096 blocks, one per row pair

// Persistent scratch. Guard word-rows 0 and 33 per batch are NEVER written
// -> stay zero from module load. All counters return to ZERO at the end of
// every launch (last block resets), so replays see a clean state.
__device__ unsigned int g_bits[B_ * NWG * W_];
__device__ int          g_wr[B_ * NW_];   // per word-row completion (16 producers)
__device__ unsigned int g_spos;
__device__ unsigned int g_done;
__device__ double       g_accT;   // sum log2(arg) over ALL pixels
__device__ double       g_accB;   // sum exp(-d2/8)*log2(1-p) over bg pixels
__device__ double       g_accC;   // sum log2(p) over fg pixels

// ---------------------------------------------------------------------------
// Single kernel, no dedicated roles. Block bi (one row-pair b,i..i+1):
//  A) packs 64 columns of word-row p = bi>>4 == 32b+wi (its OWN dependency),
//  B) signals g_wr[p], waits for the 3 word-rows it needs (producers are
//     within +/-31 blocks in launch order -> bounded forward deps, no
//     deadlock, near-zero wait since all blocks do equal pack work),
//  C) vertical clz distance -> horizontal truncated min-plus (|o|<=7)
//  D) S_pos-independent sums T,B,C; last block finalizes + resets.
// ---------------------------------------------------------------------------
__global__ void __launch_bounds__(256) bg_fused_kernel(const float* __restrict__ probs,
                                                       const float* __restrict__ targets,
                                                       float* __restrict__ out) {
    __shared__ __align__(16) unsigned int s_p[8 + W_ + 8];
    __shared__ float s_wtab[50];
    __shared__ float s_red[24];
    __shared__ int   s_cnt[2];
    unsigned int* sd = s_p + 8;

    const int t  = threadIdx.x;
    const int bi = blockIdx.x;                // 0 .. 4095
    const int b  = bi >> 9;
    const int i  = (bi & 511) << 1;           // even row; rows i, i+1
    const int wi = (bi & 511) >> 4;           // word row of rows i,i+1
    const int k  = i & 31;                    // even, <= 30
    const int j0 = t * 4;
    const int p  = bi >> 4;                   // global word-row = 32*b + wi
    const int s  = bi & 15;                   // column slice 64s .. 64s+63

    if (t < 8) {                              // pads: 49 per lane (never wins)
        s_p[t]          = 0x00310031u;
        s_p[8 + W_ + t] = 0x00310031u;
    }
    if (t < 50)                               // wb LUT over d2<=49; wtab[0]=0 (fg)
        s_wtab[t] = (t == 0) ? 0.0f : __expf((float)t * -0.125f);

    // prefetch probs (independent; in flight across pack + wait)
    const float* prA = probs + ((size_t)(b * H_) + i) * W_;
    float4 pAv = *(const float4*)(prA + j0);
    float4 pBv = *(const float4*)(prA + W_ + j0);

    // ---- A) pack: threads 0..63 each pack one column of word-row p ----
    if (t < 64) {
        const int j = 64 * s + t;
        const float* col = targets + ((size_t)(b * H_ + wi * 32)) * W_ + j;
        unsigned bits = 0u;
#pragma unroll
        for (int r = 0; r < 32; ++r)
            if (col[(size_t)r * W_] > 0.5f) bits |= (1u << r);
        g_bits[(size_t)(b * NWG + wi + 1) * W_ + j] = bits;

        int c = __popc(bits);
#pragma unroll
        for (int off = 16; off; off >>= 1)
            c += __shfl_down_sync(0xffffffffu, c, off);
        if ((t & 31) == 0) s_cnt[t >> 5] = c;
    }
    __syncthreads();                           // bits of this block visible/cta

    // ---- B) signal own slice, then wait for needed word-rows ----
    if (t == 0) {
        atomicAdd(&g_spos, (unsigned int)(s_cnt[0] + s_cnt[1]));
        __threadfence();                       // publish bits before signal
        atomicAdd(&g_wr[p], 1);
        volatile int* f = &g_wr[p];
        while (*f < 16) __nanosleep(32);
    } else if (t == 32 && wi > 0) {
        volatile int* f = &g_wr[p - 1];
        while (*f < 16) __nanosleep(32);
    } else if (t == 64 && wi < 31) {
        volatile int* f = &g_wr[p + 1];
        while (*f < 16) __nanosleep(32);
    }
    __syncthreads();
    __threadfence();                           // acquire: order g_bits reads

    // ---- C) vertical truncated distance (merged clz) ----
    const unsigned int* rb = g_bits + (size_t)(b * NWG + wi) * W_;
    uint4 w0v = *(const uint4*)(rb + j0);              // word row wi-1 (guarded)
    uint4 w1v = *(const uint4*)(rb + W_ + j0);         // word row wi
    uint4 w2v = *(const uint4*)(rb + 2 * W_ + j0);     // word row wi+1
    unsigned int w0a[4] = {w0v.x, w0v.y, w0v.z, w0v.w};
    unsigned int w1a[4] = {w1v.x, w1v.y, w1v.z, w1v.w};
    unsigned int w2a[4] = {w2v.x, w2v.y, w2v.z, w2v.w};

    uint4 stv;
    unsigned int* stp = (unsigned int*)&stv;
#pragma unroll
    for (int c = 0; c < 4; ++c) {
        unsigned int ua = __funnelshift_r(w0a[c], w1a[c], k);
        unsigned int va = __funnelshift_r(w1a[c], w2a[c], k);
        unsigned int Ca = (ua >> 1) | __brev(va);      // bit(31-d) = fg at dist d
        int ga = min(__clz(Ca), RAD);                  // clz(0)=32 -> capped
        unsigned int ub = __funnelshift_r(w0a[c], w1a[c], k + 1);
        unsigned int vb = __funnelshift_r(w1a[c], w2a[c], k + 1);
        unsigned int Cb = (ub >> 1) | __brev(vb);
        int gb = min(__clz(Cb), RAD);
        stp[c] = (unsigned int)(ga * ga) | ((unsigned int)(gb * gb) << 16);
    }
    *(uint4*)(sd + j0) = stv;
    __syncthreads();

    // ---- horizontal truncated min-plus (|o| <= 7), streamed 5x uint4 ----
    unsigned int bestp[4] = {0x7fff7fffu, 0x7fff7fffu, 0x7fff7fffu, 0x7fff7fffu};
    {
        const uint4* wp = (const uint4*)(sd + j0 - 8);   // 16B aligned
#pragma unroll
        for (int q = 0; q < 5; ++q) {
            uint4 v = wp[q];
            unsigned int wv[4] = {v.x, v.y, v.z, v.w};
#pragma unroll
            for (int r = 0; r < 4; ++r) {
                const int m = 4 * q + r;                 // window index 0..19
#pragma unroll
                for (int c = 0; c < 4; ++c) {
                    const int o = m - 8 - c;             // tap offset
                    if (o >= -RAD && o <= RAD) {
                        const unsigned int cc = (unsigned int)(o * o) * 0x00010001u;
                        bestp[c] = __viaddmin_u16x2(wv[r], cc, bestp[c]);
                    }
                }
            }
        }
    }

    // ---- D) accumulate T, B, C (exact decomposition; min(baseN+wb,1)
    //      never clips since wb <= exp(-1/8) and baseN ~ 0.02) ----
    float pa[4] = {pAv.x, pAv.y, pAv.z, pAv.w};
    float pb[4] = {pBv.x, pBv.y, pBv.z, pBv.w};

    float aT = 0.0f, aB = 0.0f, aC = 0.0f;
#pragma unroll
    for (int c = 0; c < 4; ++c) {
        const unsigned int b2 = bestp[c];
        const int dA = (int)(b2 & 0xffffu);
        const int dB = (int)(b2 >> 16);
        float wbA = s_wtab[dA];                  // 0 for fg pixels
        float wbB = s_wtab[dB];
        bool fgA = (dA == 0), fgB = (dB == 0);
        float argA = fgA ? pa[c] : (1.0f - pa[c]);
        float argB = fgB ? pb[c] : (1.0f - pb[c]);
        float lA = __log2f(argA);
        float lB = __log2f(argB);
        aT += lA;            aT += lB;
        aB += wbA * lA;      aB += wbB * lB;
        aC += fgA ? lA : 0.0f;
        aC += fgB ? lB : 0.0f;
    }

#pragma unroll
    for (int off = 16; off; off >>= 1) {
        aT += __shfl_down_sync(0xffffffffu, aT, off);
        aB += __shfl_down_sync(0xffffffffu, aB, off);
        aC += __shfl_down_sync(0xffffffffu, aC, off);
    }
    if ((t & 31) == 0) {
        int w = t >> 5;
        s_red[w] = aT; s_red[8 + w] = aB; s_red[16 + w] = aC;
    }
    __syncthreads();
    if (t < 8) {
        float vT = s_red[t], vB = s_red[8 + t], vC = s_red[16 + t];
#pragma unroll
        for (int off = 4; off; off >>= 1) {
            vT += __shfl_down_sync(0xffu, vT, off);
            vB += __shfl_down_sync(0xffu, vB, off);
            vC += __shfl_down_sync(0xffu, vC, off);
        }
        if (t == 0) {
            atomicAdd(&g_accT, (double)vT);
            atomicAdd(&g_accB, (double)vB);
            atomicAdd(&g_accC, (double)vC);
            __threadfence();
            unsigned int old = atomicAdd(&g_done, 1u);
            if (old == NBLK - 1) {               // last block: finalize + reset
                double Sp = (double)g_spos;
                double Sn = (double)NPIX - Sp;
                double w_pos = fmin((Sn + 1e-6) / (Sp + 1e-6), 1.0);
                double baseN = (Sp + 1e-6) / (Sn + 1e-6);
                double T  = *(volatile double*)&g_accT;
                double Bs = *(volatile double*)&g_accB;
                double C  = *(volatile double*)&g_accC;
                out[0] = (float)(-0.6931471805599453 *
                                 (baseN * (T - C) + Bs + w_pos * C) / (double)NPIX);
                g_accT = 0.0; g_accB = 0.0; g_accC = 0.0;
                g_spos = 0u;  g_done = 0u;
#pragma unroll 4
                for (int x = 0; x < B_ * NW_; ++x) g_wr[x] = 0;
            }
        }
    }
}

extern "C" void kernel_launch(void* const* d_in, const int* in_sizes, int n_in,
                              void* d_out, int out_size) {
    const float* probs   = (const float*)d_in[0];
    const float* targets = (const float*)d_in[1];
    float*       out     = (float*)d_out;

    bg_fused_kernel<<<NBLK, 256>>>(probs, targets, out);
}

// round 11
// speedup vs baseline: 2.6397x; 2.6397x over previous
#include <cuda_runtime.h>

#define B_   8
#define H_   1024
#define W_   1024
#define NW_  32                      // 32-bit words per column (H/32)
#define NWG  34                      // NW_ + 2 guard word-rows (always zero)
#define NPIX (B_ * H_ * W_)
#define RAD  7                       // truncation radius; rel err ~1.9e-4 << 1e-3

#define LOSS_BLOCKS (B_ * H_ / 4)    // 2048: one block per 4 rows

// Persistent scratch. Guard word-rows 0 and 33 per batch are NEVER written
// -> stay zero from module load. Counters return to ZERO at the end of every
// launch (last loss block resets them).
__device__ unsigned int g_bits[B_ * NWG * W_];
__device__ unsigned int g_spos;
__device__ unsigned int g_done;
__device__ double       g_acc;

// ---------------------------------------------------------------------------
// 1) pack targets>0.5 into per-column bitmasks + count foreground pixels.
// ---------------------------------------------------------------------------
__global__ void __launch_bounds__(256) bg_pack_kernel(const float* __restrict__ targets) {
    int tid = blockIdx.x * blockDim.x + threadIdx.x;   // 0 .. 131071
    int j2  = (tid & 511) * 2;
    int wr  = (tid >> 9) & 31;
    int b   = tid >> 14;

    const float* base = targets + ((size_t)(b * H_ + wr * 32)) * W_ + j2;
    unsigned b0 = 0, b1 = 0;
#pragma unroll 8
    for (int k = 0; k < 32; ++k) {
        float2 v = *(const float2*)(base + (size_t)k * W_);
        unsigned m = 1u << k;
        if (v.x > 0.5f) b0 |= m;
        if (v.y > 0.5f) b1 |= m;
    }
    *(uint2*)(g_bits + (size_t)(b * NWG + wr + 1) * W_ + j2) = make_uint2(b0, b1);

    int c = __popc(b0) + __popc(b1);
#pragma unroll
    for (int off = 16; off; off >>= 1)
        c += __shfl_down_sync(0xffffffffu, c, off);

    __shared__ int ssum[8];
    if ((threadIdx.x & 31) == 0) ssum[threadIdx.x >> 5] = c;
    __syncthreads();
    if (threadIdx.x < 8) {
        int v = ssum[threadIdx.x];
#pragma unroll
        for (int off = 4; off; off >>= 1)
            v += __shfl_down_sync(0xffu, v, off);
        if (threadIdx.x == 0) atomicAdd(&g_spos, (unsigned int)v);
    }
}

// ---------------------------------------------------------------------------
// Horizontal truncated min-plus over a streamed 5-uint4 window (|o| <= 7),
// then LUT-weighted loss for 2 rows x 4 cols, added to acc (log2 units).
// ---------------------------------------------------------------------------
__device__ __forceinline__ void taps_and_loss(const unsigned int* sd, int j0,
                                              const float* s_wtab,
                                              float4 pAv, float4 pBv, float& acc) {
    unsigned int bestp[4] = {0x7fff7fffu, 0x7fff7fffu, 0x7fff7fffu, 0x7fff7fffu};
    const uint4* wp = (const uint4*)(sd + j0 - 8);   // 16B aligned
#pragma unroll
    for (int q = 0; q < 5; ++q) {
        uint4 v = wp[q];
        unsigned int wv[4] = {v.x, v.y, v.z, v.w};
#pragma unroll
        for (int r = 0; r < 4; ++r) {
            const int m = 4 * q + r;                 // window index 0..19
#pragma unroll
            for (int c = 0; c < 4; ++c) {
                const int o = m - 8 - c;             // tap offset
                if (o >= -RAD && o <= RAD) {
                    const unsigned int cc = (unsigned int)(o * o) * 0x00010001u;
                    bestp[c] = __viaddmin_u16x2(wv[r], cc, bestp[c]);
                }
            }
        }
    }
    float pa[4] = {pAv.x, pAv.y, pAv.z, pAv.w};
    float pb[4] = {pBv.x, pBv.y, pBv.z, pBv.w};
#pragma unroll
    for (int c = 0; c < 4; ++c) {
        const unsigned int b2 = bestp[c];
        const int dA = (int)(b2 & 0xffffu);
        const int dB = (int)(b2 >> 16);
        float wA = s_wtab[dA];
        float wB = s_wtab[dB];
        float argA = (dA == 0) ? pa[c] : (1.0f - pa[c]);
        float argB = (dB == 0) ? pb[c] : (1.0f - pb[c]);
        acc += wA * __log2f(argA);
        acc += wB * __log2f(argB);
    }
}

// ---------------------------------------------------------------------------
// 2) loss kernel. One block = 4 adjacent rows (i = 4*blockrow), 2048 blocks.
//    Rows i..i+3 share the same 3 bit-words (k = i&31 <= 28). Two disjoint
//    shared buffers hold g^2 u16x2 for row pairs (i,i+1) and (i+2,i+3); one
//    barrier covers both. Weight via 50-entry LUT over d^2 (wtab[0] = w_pos).
//    Last block finalizes + resets counters.
// ---------------------------------------------------------------------------
__global__ void __launch_bounds__(256) bg_loss_kernel(const float* __restrict__ probs,
                                                      float* __restrict__ out) {
    __shared__ __align__(16) unsigned int s_pA[8 + W_ + 8];
    __shared__ __align__(16) unsigned int s_pB[8 + W_ + 8];
    __shared__ float s_wtab[50];
    __shared__ float s_red[8];
    unsigned int* sdA = s_pA + 8;
    unsigned int* sdB = s_pB + 8;

    const int bi = blockIdx.x;            // 0 .. 2047
    const int b  = bi >> 8;
    const int i  = (bi & 255) << 2;       // rows i .. i+3
    const int wi = i >> 5;
    const int k  = i & 31;                // multiple of 4, <= 28
    const int t  = threadIdx.x;
    const int j0 = t * 4;

    if (t < 8) {                          // pads: 49 per lane (never wins)
        s_pA[t] = 0x00310031u;  s_pA[8 + W_ + t] = 0x00310031u;
        s_pB[t] = 0x00310031u;  s_pB[8 + W_ + t] = 0x00310031u;
    }
    if (t < 50) {                         // wtab[d2]=min(baseN+exp(-d2/8),1); wtab[0]=w_pos
        const float Sp = (float)g_spos;
        const float Sn = (float)NPIX - Sp;
        float w_pos = fminf((Sn + 1e-6f) / (Sp + 1e-6f), 1.0f);
        float baseN = (Sp + 1e-6f) / (Sn + 1e-6f);
        float v = fminf(baseN + __expf((float)t * -0.125f), 1.0f);
        s_wtab[t] = (t == 0) ? w_pos : v;
    }

    // --- vertical truncated distance: 4 columns x 4 rows, shared bit words ---
    {
        const unsigned int* rb = g_bits + (size_t)(b * NWG + wi) * W_;
        uint4 w0v = *(const uint4*)(rb + j0);              // word row wi-1 (guarded)
        uint4 w1v = *(const uint4*)(rb + W_ + j0);         // word row wi
        uint4 w2v = *(const uint4*)(rb + 2 * W_ + j0);     // word row wi+1
        unsigned int w0a[4] = {w0v.x, w0v.y, w0v.z, w0v.w};
        unsigned int w1a[4] = {w1v.x, w1v.y, w1v.z, w1v.w};
        unsigned int w2a[4] = {w2v.x, w2v.y, w2v.z, w2v.w};

        uint4 stA, stB;
        unsigned int* stAp = (unsigned int*)&stA;
        unsigned int* stBp = (unsigned int*)&stB;
#pragma unroll
        for (int c = 0; c < 4; ++c) {
            int g2[4];
#pragma unroll
            for (int r = 0; r < 4; ++r) {
                unsigned int u = __funnelshift_r(w0a[c], w1a[c], k + r);
                unsigned int v = __funnelshift_r(w1a[c], w2a[c], k + r);
                unsigned int C = (u >> 1) | __brev(v);     // bit(31-d)=fg at dist d
                int g = min(__clz(C), RAD);                // clz(0)=32 -> capped
                g2[r] = g * g;                             // <= 49
            }
            stAp[c] = (unsigned int)g2[0] | ((unsigned int)g2[1] << 16);
            stBp[c] = (unsigned int)g2[2] | ((unsigned int)g2[3] << 16);
        }
        *(uint4*)(sdA + j0) = stA;
        *(uint4*)(sdB + j0) = stB;
    }

    // prefetch probs for rows i, i+1 (in flight across the barrier)
    const float* pr = probs + ((size_t)(b * H_) + i) * W_;
    float4 p0 = *(const float4*)(pr + j0);
    float4 p1 = *(const float4*)(pr + W_ + j0);

    __syncthreads();

    float acc = 0.0f;
    // phase A: rows i, i+1
    taps_and_loss(sdA, j0, s_wtab, p0, p1, acc);
    // phase B: rows i+2, i+3 (probs loaded now; latency hidden by phase A of
    // other warps)
    {
        float4 p2 = *(const float4*)(pr + 2 * W_ + j0);
        float4 p3 = *(const float4*)(pr + 3 * W_ + j0);
        taps_and_loss(sdB, j0, s_wtab, p2, p3, acc);
    }
    acc *= -0.6931471805599453f;          // log2 -> ln

    // --- block reduction -> one double atomic per block ---
#pragma unroll
    for (int off = 16; off; off >>= 1)
        acc += __shfl_down_sync(0xffffffffu, acc, off);
    if ((t & 31) == 0) s_red[t >> 5] = acc;
    __syncthreads();
    if (t < 8) {
        float v = s_red[t];
#pragma unroll
        for (int off = 4; off; off >>= 1)
            v += __shfl_down_sync(0xffu, v, off);
        if (t == 0) {
            atomicAdd(&g_acc, (double)v);
            __threadfence();
            unsigned int old = atomicAdd(&g_done, 1u);
            if (old == LOSS_BLOCKS - 1) {     // last block finalizes + resets
                double total = *(volatile double*)&g_acc;
                out[0] = (float)(total * (1.0 / (double)NPIX));
                g_acc  = 0.0;
                g_done = 0u;
                g_spos = 0u;
            }
        }
    }
}

extern "C" void kernel_launch(void* const* d_in, const int* in_sizes, int n_in,
                              void* d_out, int out_size) {
    const float* probs   = (const float*)d_in[0];
    const float* targets = (const float*)d_in[1];
    float*       out     = (float*)d_out;

    bg_pack_kernel<<<(B_ * NW_ * W_ / 2) / 256, 256>>>(targets);
    bg_loss_kernel<<<LOSS_BLOCKS, 256>>>(probs, out);
}